// round 6
// baseline (speedup 1.0000x reference)
#include <cuda_runtime.h>
#include <cstdint>

#define DIMK   256
#define NOUT   512
#define MROWS  32768
#define NEMB   255
#define NEDGE  4194304

typedef unsigned int u32;

// device scratch
__device__ float4 g_xpad[MROWS];
__device__ u32    g_Wfrag[NOUT * DIMK];   // W in tf32, mma-fragment order

// smem byte offsets (GEMM path)
#define SM_CAT  0
#define SM_CHM  512
#define SM_MSK  1024
#define SM_A0   1536
#define SM_A1   17920
#define SM_B0   34304
#define SM_B1   50688
#define SM_SIZE 67072

__device__ __forceinline__ u32 f2tf32(float v) {
    u32 r; asm("cvt.rna.tf32.f32 %0, %1;" : "=r"(r) : "f"(v)); return r;
}

__device__ __forceinline__ void mma_tf32(float* c, uint4 a, uint2 b) {
    asm volatile(
        "mma.sync.aligned.m16n8k8.row.col.f32.tf32.tf32.f32 "
        "{%0,%1,%2,%3}, {%4,%5,%6,%7}, {%8,%9}, {%0,%1,%2,%3};"
        : "+f"(c[0]), "+f"(c[1]), "+f"(c[2]), "+f"(c[3])
        : "r"(a.x), "r"(a.y), "r"(a.z), "r"(a.w), "r"(b.x), "r"(b.y));
}

// ---------------------------------------------------------------------------
// Prologue:
//   blocks 0..127  : build g_Wfrag — W transposed+tf32, laid out so the GEMM's
//                    B tile loader is a flat contiguous copy.
//     fidx layout: [nb(4)][kc(8)][tile_n(16)][tile_k(4)][lane(32)][reg(2)]
//     n = nb*128 + tile_n*8 + lane/4
//     k = kc*32 + tile_k*8 + (lane&3) + 4*reg
//   blocks 128..255: pad x -> float4
// ---------------------------------------------------------------------------
__global__ __launch_bounds__(256) void prologue_kernel(
    const float* __restrict__ x, const float* __restrict__ W)
{
    int bid = blockIdx.x, tid = threadIdx.x;
    if (bid < 128) {
        #pragma unroll
        for (int i = 0; i < 4; i++) {
            int fidx  = bid * 1024 + i * 256 + tid;
            int reg   = fidx & 1;
            int lane  = (fidx >> 1) & 31;
            int tk    = (fidx >> 6) & 3;
            int tn    = (fidx >> 8) & 15;
            int kc    = (fidx >> 12) & 7;
            int nb    = fidx >> 15;
            int n = nb * 128 + tn * 8 + (lane >> 2);
            int k = kc * 32 + tk * 8 + (lane & 3) + 4 * reg;
            g_Wfrag[fidx] = f2tf32(W[k * NOUT + n]);
        }
    } else {
        int i = (bid - 128) * 256 + tid;
        if (i < MROWS)
            g_xpad[i] = make_float4(x[3 * i], x[3 * i + 1], x[3 * i + 2], 0.f);
    }
}

// ---------------------------------------------------------------------------
// Fused: tf32 mma.sync GEMM blocks (bidx%3==0, 1024) + edge blocks (2048)
// GEMM: 128x128 tile, 8 warps (4 M x 2 N), warp tile 32x64,
//       mma m16n8k8, K staged in 8 chunks of 32, double-buffered smem,
//       A & B stored in fragment order (conflict-free LDS.128 / LDS.64).
// ---------------------------------------------------------------------------
__global__ __launch_bounds__(256, 2) void fused_kernel(
    const float* __restrict__ charges,
    const int*   __restrict__ cats,
    const float* __restrict__ nmask,
    const float* __restrict__ emb,     // [100,255]
    const float* __restrict__ bias,    // [512]
    const int*   __restrict__ edges,   // [2,E]
    float*       __restrict__ out_p,   // [32768,512]
    float*       __restrict__ radial,  // [E]
    float*       __restrict__ cd)      // [E,3]
{
    extern __shared__ char sm[];
    const int tid  = threadIdx.x;
    const int bidx = blockIdx.x;

    if (bidx % 3 == 0) {
        // =========================== GEMM ===========================
        const int g  = bidx / 3;
        const int bn = (g & 3) * 128;
        const int bm = (g >> 2) * 128;
        const int wid = tid >> 5;
        const int lid = tid & 31;
        const int warp_m = wid & 3;     // 0..3
        const int warp_n = wid >> 2;    // 0..1

        int*   s_cat = (int*)  (sm + SM_CAT);
        float* s_chm = (float*)(sm + SM_CHM);
        float* s_msk = (float*)(sm + SM_MSK);

        if (tid < 128) {
            int r = bm + tid;
            float m = nmask[r];
            s_cat[tid] = cats[r];
            s_msk[tid] = m;
            s_chm[tid] = charges[r] * m;
        }
        __syncthreads();

        u32* Abuf[2] = { (u32*)(sm + SM_A0), (u32*)(sm + SM_A1) };
        u32* Bbuf[2] = { (u32*)(sm + SM_B0), (u32*)(sm + SM_B1) };

        // A loader: fused h gather -> tf32 -> fragment layout
        //   frag float idx = ((m>>4)*4 + (k>>3))*128 + ((m&7)*4 + (k&3))*4
        //                    + ((m>>3)&1) + 2*((k>>2)&1)
        auto loadA = [&](int c, int buf) {
            u32* Ab = Abuf[buf];
            #pragma unroll
            for (int i = 0; i < 16; i++) {
                int e  = tid + i * 256;
                int k  = e & 31;
                int m  = e >> 5;
                int gk = c * 32 + k;
                float v = (gk == 0) ? s_chm[m]
                                    : __ldg(&emb[s_cat[m] * NEMB + gk - 1]) * s_msk[m];
                int off = (((m >> 4) * 4 + (k >> 3)) * 32 + ((m & 7) * 4 + (k & 3))) * 4
                          + ((m >> 3) & 1) + 2 * ((k >> 2) & 1);
                Ab[off] = f2tf32(v);
            }
        };
        // B loader: flat contiguous copy of one pre-permuted 16KB chunk
        auto loadB = [&](int c, int buf) {
            const uint4* src = (const uint4*)&g_Wfrag[((bn >> 7) * 8 + c) * 4096];
            uint4* dst = (uint4*)Bbuf[buf];
            #pragma unroll
            for (int i = 0; i < 4; i++) {
                int e = tid + i * 256;
                dst[e] = __ldg(&src[e]);
            }
        };

        float acc[2][8][4];
        #pragma unroll
        for (int t = 0; t < 2; t++)
            #pragma unroll
            for (int j = 0; j < 8; j++)
                #pragma unroll
                for (int q = 0; q < 4; q++) acc[t][j][q] = 0.f;

        loadA(0, 0);
        loadB(0, 0);
        __syncthreads();

        #pragma unroll 1
        for (int c = 0; c < 8; c++) {
            int buf = c & 1;
            if (c < 7) { loadA(c + 1, buf ^ 1); loadB(c + 1, buf ^ 1); }

            const u32* Asm = Abuf[buf];
            const u32* Bsm = Bbuf[buf];
            #pragma unroll
            for (int tk = 0; tk < 4; tk++) {
                uint4 afr[2];
                #pragma unroll
                for (int t = 0; t < 2; t++)
                    afr[t] = *(const uint4*)&Asm[(((warp_m * 2 + t) * 4 + tk) * 32 + lid) * 4];
                uint2 bfr[8];
                #pragma unroll
                for (int j = 0; j < 8; j++)
                    bfr[j] = *(const uint2*)&Bsm[(((warp_n * 8 + j) * 4 + tk) * 32 + lid) * 2];
                #pragma unroll
                for (int t = 0; t < 2; t++)
                    #pragma unroll
                    for (int j = 0; j < 8; j++)
                        mma_tf32(acc[t][j], afr[t], bfr[j]);
            }
            __syncthreads();
        }

        // epilogue: bias + direct float2 stores
        #pragma unroll
        for (int t = 0; t < 2; t++) {
            int m0 = bm + warp_m * 32 + t * 16 + (lid >> 2);
            #pragma unroll
            for (int j = 0; j < 8; j++) {
                int col = bn + warp_n * 64 + j * 8 + (lid & 3) * 2;
                float2 bv = __ldg((const float2*)&bias[col]);
                float2 v0, v1;
                v0.x = acc[t][j][0] + bv.x; v0.y = acc[t][j][1] + bv.y;
                v1.x = acc[t][j][2] + bv.x; v1.y = acc[t][j][3] + bv.y;
                *(float2*)&out_p[(size_t)m0 * NOUT + col] = v0;
                *(float2*)&out_p[(size_t)(m0 + 8) * NOUT + col] = v1;
            }
        }
    } else {
        // =========================== edges ===========================
        const int eid  = bidx - (bidx + 2) / 3;   // 0..2047
        const int base = eid * 2048;
        float* stage = (float*)sm;                // 1536 floats

        #pragma unroll 1
        for (int r = 0; r < 4; r++) {
            int e0 = base + r * 512 + tid;
            int e1 = e0 + 256;
            int ra = __ldg(&edges[e0]);
            int rb = __ldg(&edges[e1]);
            int ca = __ldg(&edges[NEDGE + e0]);
            int cb = __ldg(&edges[NEDGE + e1]);
            float4 pa = __ldg(&g_xpad[ra]);
            float4 pb = __ldg(&g_xpad[rb]);
            float4 qa = __ldg(&g_xpad[ca]);
            float4 qb = __ldg(&g_xpad[cb]);

            float dax = pa.x - qa.x, day = pa.y - qa.y, daz = pa.z - qa.z;
            float dbx = pb.x - qb.x, dby = pb.y - qb.y, dbz = pb.z - qb.z;
            float rada = dax * dax + day * day + daz * daz;
            float radb = dbx * dbx + dby * dby + dbz * dbz;
            float inva = 1.0f / (sqrtf(rada + 1e-8f) + 1.0f);
            float invb = 1.0f / (sqrtf(radb + 1e-8f) + 1.0f);

            radial[e0] = rada;
            radial[e1] = radb;

            stage[tid * 3 + 0] = dax * inva;
            stage[tid * 3 + 1] = day * inva;
            stage[tid * 3 + 2] = daz * inva;
            stage[(tid + 256) * 3 + 0] = dbx * invb;
            stage[(tid + 256) * 3 + 1] = dby * invb;
            stage[(tid + 256) * 3 + 2] = dbz * invb;
            __syncthreads();

            // 1536 floats = 384 float4 coalesced
            float4* dst = (float4*)(cd + (size_t)(base + r * 512) * 3);
            const float4* s4 = (const float4*)stage;
            dst[tid] = s4[tid];
            if (tid < 128) dst[256 + tid] = s4[256 + tid];
            __syncthreads();
        }
    }
}

// ---------------------------------------------------------------------------
// inputs: 0 x, 1 categories, 2 charges, 3 edges, 4 node_mask, 5 edge_mask,
//         6 emb_table, 7 W, 8 b_lin
// output: parameters [32768*512] | radial [E] | coord_diff [E*3]
// ---------------------------------------------------------------------------
extern "C" void kernel_launch(void* const* d_in, const int* in_sizes, int n_in,
                              void* d_out, int out_size)
{
    const float* x       = (const float*)d_in[0];
    const int*   cats    = (const int*)  d_in[1];
    const float* charges = (const float*)d_in[2];
    const int*   edges   = (const int*)  d_in[3];
    const float* nmask   = (const float*)d_in[4];
    const float* emb     = (const float*)d_in[6];
    const float* W       = (const float*)d_in[7];
    const float* bias    = (const float*)d_in[8];

    float* out        = (float*)d_out;
    float* out_params = out;
    float* out_radial = out + (size_t)MROWS * NOUT;
    float* out_cd     = out_radial + NEDGE;

    cudaFuncSetAttribute(fused_kernel, cudaFuncAttributeMaxDynamicSharedMemorySize, SM_SIZE);

    prologue_kernel<<<256, 256>>>(x, W);
    fused_kernel<<<3072, 256, SM_SIZE>>>(charges, cats, nmask, emb, bias, edges,
                                         out_params, out_radial, out_cd);
}

// round 7
// speedup vs baseline: 1.0827x; 1.0827x over previous
#include <cuda_runtime.h>
#include <cstdint>

#define DIMK   256
#define NOUT   512
#define MROWS  32768
#define NEMB   255
#define NEDGE  4194304

typedef unsigned int u32;

// device scratch
__device__ float4 g_xpad[MROWS];
__device__ u32    g_Wfrag[NOUT * DIMK];           // W  tf32, fragment order
__device__ u32    g_Afrag[(size_t)MROWS * DIMK];  // h  tf32, fragment order (32MB)

// smem: 3 stages x (A 16KB + B 16KB)
#define STAGE_BYTES 32768
#define SM_SIZE     (3 * STAGE_BYTES)

__device__ __forceinline__ u32 f2tf32(float v) {
    u32 r; asm("cvt.rna.tf32.f32 %0, %1;" : "=r"(r) : "f"(v)); return r;
}
__device__ __forceinline__ u32 smem_u32(const void* p) {
    u32 a;
    asm("{ .reg .u64 t; cvta.to.shared.u64 t, %1; cvt.u32.u64 %0, t; }" : "=r"(a) : "l"(p));
    return a;
}
__device__ __forceinline__ void cp16(u32 dst, const void* src) {
    asm volatile("cp.async.cg.shared.global [%0], [%1], 16;" :: "r"(dst), "l"(src));
}
#define CP_COMMIT() asm volatile("cp.async.commit_group;" ::: "memory")
#define CP_WAIT2()  asm volatile("cp.async.wait_group 2;" ::: "memory")

__device__ __forceinline__ void mma_tf32(float* c, uint4 a, uint2 b) {
    asm volatile(
        "mma.sync.aligned.m16n8k8.row.col.f32.tf32.tf32.f32 "
        "{%0,%1,%2,%3}, {%4,%5,%6,%7}, {%8,%9}, {%0,%1,%2,%3};"
        : "+f"(c[0]), "+f"(c[1]), "+f"(c[2]), "+f"(c[3])
        : "r"(a.x), "r"(a.y), "r"(a.z), "r"(a.w), "r"(b.x), "r"(b.y));
}

// ---------------------------------------------------------------------------
// Prologue.
// blocks 0..1023     : build g_Afrag (h matrix, tf32, fragment order)
// blocks 1024..1151  : build g_Wfrag
// blocks 1152..1279  : pad x -> float4
//
// Fragment layout (per 128x32 chunk = 4096 u32):
//   off = frag*128 + lane*4 + reg,  frag = tile_m*4 + tile_k (tile_m<8, tile_k<4)
//   m = mb*128 + tile_m*16 + (lane>>2) + 8*(reg&1)
//   k = kc*32  + tile_k*8  + (lane&3)  + 4*(reg>>1)
//   chunk index = mb*8 + kc   (A)    /   nb*8 + kc  (B, n in place of m)
// ---------------------------------------------------------------------------
__global__ __launch_bounds__(256) void prologue_kernel(
    const float* __restrict__ x,
    const float* __restrict__ W,
    const float* __restrict__ charges,
    const int*   __restrict__ cats,
    const float* __restrict__ nmask,
    const float* __restrict__ emb)
{
    int bid = blockIdx.x, tid = threadIdx.x;
    if (bid < 1024) {
        // each thread writes uint4 (4 regs of one lane/frag)
        #pragma unroll
        for (int i = 0; i < 8; i++) {
            int q     = bid * 2048 + i * 256 + tid;   // uint4 index
            int lane  = q & 31;
            int frag  = (q >> 5) & 31;
            int kc    = (q >> 10) & 7;
            int mb    = q >> 13;
            int tile_m = frag >> 2;
            int tile_k = frag & 3;
            int m0 = mb * 128 + tile_m * 16 + (lane >> 2);
            int k0 = kc * 32 + tile_k * 8 + (lane & 3);
            uint4 v;
            u32* vv = (u32*)&v;
            #pragma unroll
            for (int reg = 0; reg < 4; reg++) {
                int m = m0 + 8 * (reg & 1);
                int k = k0 + 4 * (reg >> 1);
                float msk = __ldg(&nmask[m]);
                float h = (k == 0) ? __ldg(&charges[m]) * msk
                                   : __ldg(&emb[__ldg(&cats[m]) * NEMB + k - 1]) * msk;
                vv[reg] = f2tf32(h);
            }
            ((uint4*)g_Afrag)[q] = v;
        }
    } else if (bid < 1152) {
        int b = bid - 1024;
        #pragma unroll
        for (int i = 0; i < 4; i++) {
            int fidx  = b * 1024 + i * 256 + tid;
            int reg   = fidx & 1;
            int lane  = (fidx >> 1) & 31;
            int tk    = (fidx >> 6) & 3;
            int tn    = (fidx >> 8) & 15;
            int kc    = (fidx >> 12) & 7;
            int nb    = fidx >> 15;
            int n = nb * 128 + tn * 8 + (lane >> 2);
            int k = kc * 32 + tk * 8 + (lane & 3) + 4 * reg;
            g_Wfrag[fidx] = f2tf32(W[k * NOUT + n]);
        }
    } else {
        int i = (bid - 1152) * 256 + tid;
        if (i < MROWS)
            g_xpad[i] = make_float4(x[3 * i], x[3 * i + 1], x[3 * i + 2], 0.f);
    }
}

// ---------------------------------------------------------------------------
// Fused: tf32 mma.sync GEMM blocks (bidx%3==0, 1024) + edge blocks (2048).
// GEMM mainloop: pure cp.async (3-stage) + HMMA. 128x128 tile, 8 warps.
// ---------------------------------------------------------------------------
__global__ __launch_bounds__(256, 2) void fused_kernel(
    const float* __restrict__ bias,    // [512]
    const int*   __restrict__ edges,   // [2,E]
    float*       __restrict__ out_p,   // [32768,512]
    float*       __restrict__ radial,  // [E]
    float*       __restrict__ cd)      // [E,3]
{
    extern __shared__ char sm[];
    const int tid  = threadIdx.x;
    const int bidx = blockIdx.x;

    if (bidx % 3 == 0) {
        // =========================== GEMM ===========================
        const int g  = bidx / 3;
        const int bn = (g & 3) * 128;
        const int bm = (g >> 2) * 128;
        const int wid = tid >> 5;
        const int lid = tid & 31;
        const int warp_m = wid & 3;
        const int warp_n = wid >> 2;
        const u32 smb = smem_u32(sm);

        const uint4* Asrc = (const uint4*)g_Afrag + (size_t)((bm >> 7) * 8) * 1024;
        const uint4* Bsrc = (const uint4*)g_Wfrag + (size_t)((bn >> 7) * 8) * 1024;

        // stage loader: chunk c -> stage s (A 16KB then B 16KB), 8 cp.async/thread
        auto loadAB = [&](int c, int s) {
            u32 base = smb + s * STAGE_BYTES;
            const uint4* a = Asrc + c * 1024;
            const uint4* b = Bsrc + c * 1024;
            #pragma unroll
            for (int i = 0; i < 4; i++) {
                int e = tid + i * 256;
                cp16(base + e * 16, a + e);
                cp16(base + 16384 + e * 16, b + e);
            }
            CP_COMMIT();
        };

        float acc[2][8][4];
        #pragma unroll
        for (int t = 0; t < 2; t++)
            #pragma unroll
            for (int j = 0; j < 8; j++)
                #pragma unroll
                for (int q = 0; q < 4; q++) acc[t][j][q] = 0.f;

        loadAB(0, 0);
        loadAB(1, 1);
        loadAB(2, 2);

        #pragma unroll 1
        for (int c = 0; c < 8; c++) {
            int s = c % 3;
            CP_WAIT2();
            __syncthreads();

            const u32* Asm = (const u32*)(sm + s * STAGE_BYTES);
            const u32* Bsm = (const u32*)(sm + s * STAGE_BYTES + 16384);
            #pragma unroll
            for (int tk = 0; tk < 4; tk++) {
                uint4 afr[2];
                #pragma unroll
                for (int t = 0; t < 2; t++)
                    afr[t] = *(const uint4*)&Asm[(((warp_m * 2 + t) * 4 + tk) * 32 + lid) * 4];
                uint2 bfr[8];
                #pragma unroll
                for (int j = 0; j < 8; j++)
                    bfr[j] = *(const uint2*)&Bsm[(((warp_n * 8 + j) * 4 + tk) * 32 + lid) * 2];
                #pragma unroll
                for (int t = 0; t < 2; t++)
                    #pragma unroll
                    for (int j = 0; j < 8; j++)
                        mma_tf32(acc[t][j], afr[t], bfr[j]);
            }
            __syncthreads();
            if (c + 3 < 8) loadAB(c + 3, s);
        }

        // epilogue: bias + float2 stores
        #pragma unroll
        for (int t = 0; t < 2; t++) {
            int m0 = bm + warp_m * 32 + t * 16 + (lid >> 2);
            #pragma unroll
            for (int j = 0; j < 8; j++) {
                int col = bn + warp_n * 64 + j * 8 + (lid & 3) * 2;
                float2 bv = __ldg((const float2*)&bias[col]);
                float2 v0, v1;
                v0.x = acc[t][j][0] + bv.x; v0.y = acc[t][j][1] + bv.y;
                v1.x = acc[t][j][2] + bv.x; v1.y = acc[t][j][3] + bv.y;
                *(float2*)&out_p[(size_t)m0 * NOUT + col] = v0;
                *(float2*)&out_p[(size_t)(m0 + 8) * NOUT + col] = v1;
            }
        }
    } else {
        // =========================== edges ===========================
        const int eid  = bidx - (bidx + 2) / 3;   // 0..2047
        const int base = eid * 2048;
        float* stage = (float*)sm;                // 1536 floats

        #pragma unroll 1
        for (int r = 0; r < 4; r++) {
            int e0 = base + r * 512 + tid;
            int e1 = e0 + 256;
            int ra = __ldg(&edges[e0]);
            int rb = __ldg(&edges[e1]);
            int ca = __ldg(&edges[NEDGE + e0]);
            int cb = __ldg(&edges[NEDGE + e1]);
            float4 pa = __ldg(&g_xpad[ra]);
            float4 pb = __ldg(&g_xpad[rb]);
            float4 qa = __ldg(&g_xpad[ca]);
            float4 qb = __ldg(&g_xpad[cb]);

            float dax = pa.x - qa.x, day = pa.y - qa.y, daz = pa.z - qa.z;
            float dbx = pb.x - qb.x, dby = pb.y - qb.y, dbz = pb.z - qb.z;
            float rada = dax * dax + day * day + daz * daz;
            float radb = dbx * dbx + dby * dby + dbz * dbz;
            float inva = 1.0f / (sqrtf(rada + 1e-8f) + 1.0f);
            float invb = 1.0f / (sqrtf(radb + 1e-8f) + 1.0f);

            radial[e0] = rada;
            radial[e1] = radb;

            stage[tid * 3 + 0] = dax * inva;
            stage[tid * 3 + 1] = day * inva;
            stage[tid * 3 + 2] = daz * inva;
            stage[(tid + 256) * 3 + 0] = dbx * invb;
            stage[(tid + 256) * 3 + 1] = dby * invb;
            stage[(tid + 256) * 3 + 2] = dbz * invb;
            __syncthreads();

            float4* dst = (float4*)(cd + (size_t)(base + r * 512) * 3);
            const float4* s4 = (const float4*)stage;
            dst[tid] = s4[tid];
            if (tid < 128) dst[256 + tid] = s4[256 + tid];
            __syncthreads();
        }
    }
}

// ---------------------------------------------------------------------------
// inputs: 0 x, 1 categories, 2 charges, 3 edges, 4 node_mask, 5 edge_mask,
//         6 emb_table, 7 W, 8 b_lin
// output: parameters [32768*512] | radial [E] | coord_diff [E*3]
// ---------------------------------------------------------------------------
extern "C" void kernel_launch(void* const* d_in, const int* in_sizes, int n_in,
                              void* d_out, int out_size)
{
    const float* x       = (const float*)d_in[0];
    const int*   cats    = (const int*)  d_in[1];
    const float* charges = (const float*)d_in[2];
    const int*   edges   = (const int*)  d_in[3];
    const float* nmask   = (const float*)d_in[4];
    const float* emb     = (const float*)d_in[6];
    const float* W       = (const float*)d_in[7];
    const float* bias    = (const float*)d_in[8];

    float* out        = (float*)d_out;
    float* out_params = out;
    float* out_radial = out + (size_t)MROWS * NOUT;
    float* out_cd     = out_radial + NEDGE;

    cudaFuncSetAttribute(fused_kernel, cudaFuncAttributeMaxDynamicSharedMemorySize, SM_SIZE);

    prologue_kernel<<<1280, 256>>>(x, W, charges, cats, nmask, emb);
    fused_kernel<<<3072, 256, SM_SIZE>>>(bias, edges, out_params, out_radial, out_cd);
}

// round 8
// speedup vs baseline: 1.6119x; 1.4888x over previous
#include <cuda_runtime.h>
#include <cstdint>

#define DIMK   256
#define NOUT   512
#define MROWS  32768
#define NEMB   255
#define NEDGE  4194304

typedef unsigned int u32;

// device scratch
__device__ float4 g_xpad[MROWS];
__device__ u32    g_Wfrag[NOUT * DIMK];           // W  tf32, fragment order
__device__ u32    g_Afrag[(size_t)MROWS * DIMK];  // h  tf32, fragment order (32MB)

// smem: 3 stages x (A 16KB + B 16KB)
#define STAGE_BYTES 32768
#define SM_SIZE     (3 * STAGE_BYTES)

__device__ __forceinline__ u32 f2tf32(float v) {
    u32 r; asm("cvt.rna.tf32.f32 %0, %1;" : "=r"(r) : "f"(v)); return r;
}
__device__ __forceinline__ u32 smem_u32(const void* p) {
    u32 a;
    asm("{ .reg .u64 t; cvta.to.shared.u64 t, %1; cvt.u32.u64 %0, t; }" : "=r"(a) : "l"(p));
    return a;
}
__device__ __forceinline__ void cp16(u32 dst, const void* src) {
    asm volatile("cp.async.cg.shared.global [%0], [%1], 16;" :: "r"(dst), "l"(src));
}
#define CP_COMMIT() asm volatile("cp.async.commit_group;" ::: "memory")
#define CP_WAIT2()  asm volatile("cp.async.wait_group 2;" ::: "memory")

__device__ __forceinline__ void mma_tf32(float* c, uint4 a, uint2 b) {
    asm volatile(
        "mma.sync.aligned.m16n8k8.row.col.f32.tf32.tf32.f32 "
        "{%0,%1,%2,%3}, {%4,%5,%6,%7}, {%8,%9}, {%0,%1,%2,%3};"
        : "+f"(c[0]), "+f"(c[1]), "+f"(c[2]), "+f"(c[3])
        : "r"(a.x), "r"(a.y), "r"(a.z), "r"(a.w), "r"(b.x), "r"(b.y));
}

// ---------------------------------------------------------------------------
// Prologue.
// blocks 0..1023     : build g_Afrag (h matrix, tf32, fragment order)
// blocks 1024..1151  : build g_Wfrag
// blocks 1152..1279  : pad x -> float4
//
// Fragment layout (per 128x32 chunk = 4096 u32):
//   off = frag*128 + lane*4 + reg,  frag = tile_m*4 + tile_k (tile_m<8, tile_k<4)
//   m = mb*128 + tile_m*16 + (lane>>2) + 8*(reg&1)
//   k = kc*32  + tile_k*8  + (lane&3)  + 4*(reg>>1)
//   chunk index = mb*8 + kc   (A)    /   nb*8 + kc  (B, n in place of m)
// ---------------------------------------------------------------------------
__global__ __launch_bounds__(256) void prologue_kernel(
    const float* __restrict__ x,
    const float* __restrict__ W,
    const float* __restrict__ charges,
    const int*   __restrict__ cats,
    const float* __restrict__ nmask,
    const float* __restrict__ emb)
{
    int bid = blockIdx.x, tid = threadIdx.x;
    if (bid < 1024) {
        // each thread writes uint4 (4 regs of one lane/frag)
        #pragma unroll
        for (int i = 0; i < 8; i++) {
            int q     = bid * 2048 + i * 256 + tid;   // uint4 index
            int lane  = q & 31;
            int frag  = (q >> 5) & 31;
            int kc    = (q >> 10) & 7;
            int mb    = q >> 13;
            int tile_m = frag >> 2;
            int tile_k = frag & 3;
            int m0 = mb * 128 + tile_m * 16 + (lane >> 2);
            int k0 = kc * 32 + tile_k * 8 + (lane & 3);
            uint4 v;
            u32* vv = (u32*)&v;
            #pragma unroll
            for (int reg = 0; reg < 4; reg++) {
                int m = m0 + 8 * (reg & 1);
                int k = k0 + 4 * (reg >> 1);
                float msk = __ldg(&nmask[m]);
                float h = (k == 0) ? __ldg(&charges[m]) * msk
                                   : __ldg(&emb[__ldg(&cats[m]) * NEMB + k - 1]) * msk;
                vv[reg] = f2tf32(h);
            }
            ((uint4*)g_Afrag)[q] = v;
        }
    } else if (bid < 1152) {
        int b = bid - 1024;
        #pragma unroll
        for (int i = 0; i < 4; i++) {
            int fidx  = b * 1024 + i * 256 + tid;
            int reg   = fidx & 1;
            int lane  = (fidx >> 1) & 31;
            int tk    = (fidx >> 6) & 3;
            int tn    = (fidx >> 8) & 15;
            int kc    = (fidx >> 12) & 7;
            int nb    = fidx >> 15;
            int n = nb * 128 + tn * 8 + (lane >> 2);
            int k = kc * 32 + tk * 8 + (lane & 3) + 4 * reg;
            g_Wfrag[fidx] = f2tf32(W[k * NOUT + n]);
        }
    } else {
        int i = (bid - 1152) * 256 + tid;
        if (i < MROWS)
            g_xpad[i] = make_float4(x[3 * i], x[3 * i + 1], x[3 * i + 2], 0.f);
    }
}

// ---------------------------------------------------------------------------
// Fused: tf32 mma.sync GEMM blocks (bidx%3==0, 1024) + edge blocks (2048).
// GEMM mainloop: pure cp.async (3-stage) + HMMA. 128x128 tile, 8 warps.
// ---------------------------------------------------------------------------
__global__ __launch_bounds__(256, 2) void fused_kernel(
    const float* __restrict__ bias,    // [512]
    const int*   __restrict__ edges,   // [2,E]
    float*       __restrict__ out_p,   // [32768,512]
    float*       __restrict__ radial,  // [E]
    float*       __restrict__ cd)      // [E,3]
{
    extern __shared__ char sm[];
    const int tid  = threadIdx.x;
    const int bidx = blockIdx.x;

    if (bidx % 3 == 0) {
        // =========================== GEMM ===========================
        const int g  = bidx / 3;
        const int bn = (g & 3) * 128;
        const int bm = (g >> 2) * 128;
        const int wid = tid >> 5;
        const int lid = tid & 31;
        const int warp_m = wid & 3;
        const int warp_n = wid >> 2;
        const u32 smb = smem_u32(sm);

        const uint4* Asrc = (const uint4*)g_Afrag + (size_t)((bm >> 7) * 8) * 1024;
        const uint4* Bsrc = (const uint4*)g_Wfrag + (size_t)((bn >> 7) * 8) * 1024;

        // stage loader: chunk c -> stage s (A 16KB then B 16KB), 8 cp.async/thread
        auto loadAB = [&](int c, int s) {
            u32 base = smb + s * STAGE_BYTES;
            const uint4* a = Asrc + c * 1024;
            const uint4* b = Bsrc + c * 1024;
            #pragma unroll
            for (int i = 0; i < 4; i++) {
                int e = tid + i * 256;
                cp16(base + e * 16, a + e);
                cp16(base + 16384 + e * 16, b + e);
            }
            CP_COMMIT();
        };

        float acc[2][8][4];
        #pragma unroll
        for (int t = 0; t < 2; t++)
            #pragma unroll
            for (int j = 0; j < 8; j++)
                #pragma unroll
                for (int q = 0; q < 4; q++) acc[t][j][q] = 0.f;

        loadAB(0, 0);
        loadAB(1, 1);
        loadAB(2, 2);

        #pragma unroll 1
        for (int c = 0; c < 8; c++) {
            int s = c % 3;
            CP_WAIT2();
            __syncthreads();

            const u32* Asm = (const u32*)(sm + s * STAGE_BYTES);
            const u32* Bsm = (const u32*)(sm + s * STAGE_BYTES + 16384);
            #pragma unroll
            for (int tk = 0; tk < 4; tk++) {
                uint4 afr[2];
                #pragma unroll
                for (int t = 0; t < 2; t++)
                    afr[t] = *(const uint4*)&Asm[(((warp_m * 2 + t) * 4 + tk) * 32 + lid) * 4];
                uint2 bfr[8];
                #pragma unroll
                for (int j = 0; j < 8; j++)
                    bfr[j] = *(const uint2*)&Bsm[(((warp_n * 8 + j) * 4 + tk) * 32 + lid) * 2];
                #pragma unroll
                for (int t = 0; t < 2; t++)
                    #pragma unroll
                    for (int j = 0; j < 8; j++)
                        mma_tf32(acc[t][j], afr[t], bfr[j]);
            }
            __syncthreads();
            if (c + 3 < 8) loadAB(c + 3, s);
        }

        // epilogue: bias + float2 stores
        #pragma unroll
        for (int t = 0; t < 2; t++) {
            int m0 = bm + warp_m * 32 + t * 16 + (lid >> 2);
            #pragma unroll
            for (int j = 0; j < 8; j++) {
                int col = bn + warp_n * 64 + j * 8 + (lid & 3) * 2;
                float2 bv = __ldg((const float2*)&bias[col]);
                float2 v0, v1;
                v0.x = acc[t][j][0] + bv.x; v0.y = acc[t][j][1] + bv.y;
                v1.x = acc[t][j][2] + bv.x; v1.y = acc[t][j][3] + bv.y;
                *(float2*)&out_p[(size_t)m0 * NOUT + col] = v0;
                *(float2*)&out_p[(size_t)(m0 + 8) * NOUT + col] = v1;
            }
        }
    } else {
        // =========================== edges ===========================
        const int eid  = bidx - (bidx + 2) / 3;   // 0..2047
        const int base = eid * 2048;
        float* stage = (float*)sm;                // 1536 floats

        #pragma unroll 1
        for (int r = 0; r < 4; r++) {
            int e0 = base + r * 512 + tid;
            int e1 = e0 + 256;
            int ra = __ldg(&edges[e0]);
            int rb = __ldg(&edges[e1]);
            int ca = __ldg(&edges[NEDGE + e0]);
            int cb = __ldg(&edges[NEDGE + e1]);
            float4 pa = __ldg(&g_xpad[ra]);
            float4 pb = __ldg(&g_xpad[rb]);
            float4 qa = __ldg(&g_xpad[ca]);
            float4 qb = __ldg(&g_xpad[cb]);

            float dax = pa.x - qa.x, day = pa.y - qa.y, daz = pa.z - qa.z;
            float dbx = pb.x - qb.x, dby = pb.y - qb.y, dbz = pb.z - qb.z;
            float rada = dax * dax + day * day + daz * daz;
            float radb = dbx * dbx + dby * dby + dbz * dbz;
            float inva = 1.0f / (sqrtf(rada + 1e-8f) + 1.0f);
            float invb = 1.0f / (sqrtf(radb + 1e-8f) + 1.0f);

            radial[e0] = rada;
            radial[e1] = radb;

            stage[tid * 3 + 0] = dax * inva;
            stage[tid * 3 + 1] = day * inva;
            stage[tid * 3 + 2] = daz * inva;
            stage[(tid + 256) * 3 + 0] = dbx * invb;
            stage[(tid + 256) * 3 + 1] = dby * invb;
            stage[(tid + 256) * 3 + 2] = dbz * invb;
            __syncthreads();

            float4* dst = (float4*)(cd + (size_t)(base + r * 512) * 3);
            const float4* s4 = (const float4*)stage;
            dst[tid] = s4[tid];
            if (tid < 128) dst[256 + tid] = s4[256 + tid];
            __syncthreads();
        }
    }
}

// ---------------------------------------------------------------------------
// inputs: 0 x, 1 categories, 2 charges, 3 edges, 4 node_mask, 5 edge_mask,
//         6 emb_table, 7 W, 8 b_lin
// output: parameters [32768*512] | radial [E] | coord_diff [E*3]
// ---------------------------------------------------------------------------
extern "C" void kernel_launch(void* const* d_in, const int* in_sizes, int n_in,
                              void* d_out, int out_size)
{
    const float* x       = (const float*)d_in[0];
    const int*   cats    = (const int*)  d_in[1];
    const float* charges = (const float*)d_in[2];
    const int*   edges   = (const int*)  d_in[3];
    const float* nmask   = (const float*)d_in[4];
    const float* emb     = (const float*)d_in[6];
    const float* W       = (const float*)d_in[7];
    const float* bias    = (const float*)d_in[8];

    float* out        = (float*)d_out;
    float* out_params = out;
    float* out_radial = out + (size_t)MROWS * NOUT;
    float* out_cd     = out_radial + NEDGE;

    cudaFuncSetAttribute(fused_kernel, cudaFuncAttributeMaxDynamicSharedMemorySize, SM_SIZE);

    prologue_kernel<<<1280, 256>>>(x, W, charges, cats, nmask, emb);
    fused_kernel<<<3072, 256, SM_SIZE>>>(bias, edges, out_params, out_radial, out_cd);
}